// round 16
// baseline (speedup 1.0000x reference)
#include <cuda_runtime.h>
#include <cuda_fp16.h>
#include <math.h>
#include <stdint.h>

// Problem constants: H=1024, B=1024, S=128 (T=127), E=6, V=3, C=10
#define HD   1024
#define BD   1024
#define SD   128
#define TD   127
#define ED   6
#define VD   3
#define CD   10

#define NB   64       // batch cols per block
#define BK   64       // k per chunk
#define NCH  (HD/BK)  // 16 chunks

// Stage: A 128x64 f16 (16KB) + B 64x64 f16 (8KB) = 24KB; 2 stages = 48KB.
#define STAGE_BYTES 24576
#define B_OFF       16384
#define SQ_OFF      (2 * STAGE_BYTES)            // Q tile: 4*3*32 f32 = 1536 B
#define SMEM_STEP   (2 * STAGE_BYTES + 1536)

// ---------------------------------------------------------------------------
// Static device scratch (no allocations allowed).
// g_Wr gate-major rows: block row r = wm*64 + gate*16 + hl  ->  W_gate[h = y*32 + wm*16 + hl]
__device__ __half g_Wr[32u * 128 * HD];
__device__ __half g_hT2[2u * BD * HD];    // PING-PONG h transposed fp16 [plane][b][h]
__device__ float  g_c[HD * BD];           // cell state [h][b]
__device__ float  g_Q[4 * VD * HD];       // input contribution + bias [gate][v][h]
__device__ int    g_tokT[SD * BD];        // tokens transposed [t][b]
// Release flags: g_flag[(bx*32 + hblk)*32], 128B padded, single writer each.
__device__ int    g_flag[16 * 32 * 32];

// ---------------------------------------------------------------------------
__device__ __forceinline__ uint32_t smem_u32(const void* p) {
    uint32_t a;
    asm("{ .reg .u64 t; cvta.to.shared.u64 t, %1; cvt.u32.u64 %0, t; }" : "=r"(a) : "l"(p));
    return a;
}

__device__ __forceinline__ void cp16(uint32_t dst, const void* src) {
    asm volatile("cp.async.cg.shared.global [%0], [%1], 16;" :: "r"(dst), "l"(src));
}
__device__ __forceinline__ void cp_commit() {
    asm volatile("cp.async.commit_group;" ::: "memory");
}
template <int N> __device__ __forceinline__ void cp_wait() {
    asm volatile("cp.async.wait_group %0;" :: "n"(N) : "memory");
}

__device__ __forceinline__ void ldm_x4(uint32_t r[4], uint32_t addr) {
    asm volatile("ldmatrix.sync.aligned.m8n8.x4.shared.b16 {%0,%1,%2,%3}, [%4];"
                 : "=r"(r[0]), "=r"(r[1]), "=r"(r[2]), "=r"(r[3]) : "r"(addr));
}

// f16-accumulate HMMA: D (2 regs, f16x2) = A (4 regs) * B (2 regs) + D.
__device__ __forceinline__ void mma_f16acc(uint32_t c[2], const uint32_t a[4],
                                           const uint32_t b0, const uint32_t b1) {
    asm volatile(
        "mma.sync.aligned.m16n8k16.row.col.f16.f16.f16.f16 "
        "{%0,%1}, {%2,%3,%4,%5}, {%6,%7}, {%0,%1};"
        : "+r"(c[0]), "+r"(c[1])
        : "r"(a[0]), "r"(a[1]), "r"(a[2]), "r"(a[3]), "r"(b0), "r"(b1));
}

__device__ __forceinline__ int ld_acq(const int* p) {
    int v;
    asm volatile("ld.acquire.gpu.s32 %0, [%1];" : "=r"(v) : "l"(p) : "memory");
    return v;
}
__device__ __forceinline__ void st_rel(int* p, int v) {
    asm volatile("st.release.gpu.s32 [%0], %1;" :: "l"(p), "r"(v) : "memory");
}
__device__ __forceinline__ void wait_chunk(int bx, int ch, int t) {
    const int* f0 = &g_flag[((bx << 5) + (ch << 1)) << 5];
    const int* f1 = f0 + 32;
    while (ld_acq(f0) < t) __nanosleep(32);
    while (ld_acq(f1) < t) __nanosleep(32);
}

__device__ __forceinline__ float sigm(float v) { return 1.0f / (1.0f + __expf(-v)); }
__device__ __forceinline__ float ftanh(float x) {
    float e = __expf(-2.0f * fabsf(x));
    float r = (1.0f - e) / (1.0f + e);
    return copysignf(r, x);
}
__device__ __forceinline__ float qsel(const float* q, int t) {
    return t == 0 ? q[0] : (t == 1 ? q[1] : q[2]);
}

// Swizzled byte offset inside a 128B-row tile: (r, c16) with c16 in [0,8)
__device__ __forceinline__ uint32_t SW(int r, int c16) {
    return (uint32_t)(r * 128) + ((uint32_t)(c16 << 4) ^ (uint32_t)((r & 7) << 4));
}

// ---------------------------------------------------------------------------
// One-time init kernels
__global__ void init_state(const float* __restrict__ h0, const float* __restrict__ c0,
                           const int* __restrict__ x) {
    int i = blockIdx.x * blockDim.x + threadIdx.x;
    if (i < HD * BD) {
        g_c[i] = c0[i];
        int h = i >> 10, b = i & (BD - 1);
        g_hT2[(size_t)b * HD + h] = __float2half(h0[i]);   // plane 0
    }
    if (i < SD * BD) {
        int t = i >> 10, b = i & (BD - 1);
        g_tokT[(size_t)t * BD + b] = x[(size_t)b * SD + t];
    }
    if (i < 16 * 32 * 32) g_flag[i] = 0;
}

// Gate-major weight pack: block row r = wm*64 + g*16 + hl -> W_g[h = y*32 + wm*16 + hl]
__global__ void prep_weights(const float* __restrict__ W0, const float* __restrict__ W1,
                             const float* __restrict__ W2, const float* __restrict__ W3) {
    size_t e = (size_t)(blockIdx.x * blockDim.x + threadIdx.x) * 4;
    if (e >= 32ull * 128 * HD) return;
    int k = (int)(e & (HD - 1));
    int r = (int)((e >> 10) & 127);
    int y = (int)(e >> 17);
    int wm = r >> 6;
    int g  = (r >> 4) & 3;
    int hl = r & 15;
    int h  = y * 32 + wm * 16 + hl;
    const float* W = g == 0 ? W0 : g == 1 ? W1 : g == 2 ? W2 : W3;
    float4 v = *reinterpret_cast<const float4*>(&W[(size_t)h * HD + k]);
    *reinterpret_cast<__half2*>(&g_Wr[e])     = __floats2half2_rn(v.x, v.y);
    *reinterpret_cast<__half2*>(&g_Wr[e + 2]) = __floats2half2_rn(v.z, v.w);
}

__global__ void build_Q(const float* __restrict__ emb,
                        const float* __restrict__ Wgx, const float* __restrict__ bg,
                        const float* __restrict__ Wix, const float* __restrict__ bi,
                        const float* __restrict__ Wfx, const float* __restrict__ bf,
                        const float* __restrict__ Wox, const float* __restrict__ bo) {
    int i = blockIdx.x * blockDim.x + threadIdx.x;
    if (i >= 4 * VD * HD) return;
    int gate = i / (VD * HD);
    int r = i % (VD * HD);
    int v = r >> 10;
    int h = r & (HD - 1);
    const float* Wx = (gate == 0) ? Wgx : (gate == 1) ? Wix : (gate == 2) ? Wfx : Wox;
    const float* bb = (gate == 0) ? bg  : (gate == 1) ? bi  : (gate == 2) ? bf  : bo;
    float s = bb[h];
#pragma unroll
    for (int e = 0; e < ED; e++) s += Wx[h * ED + e] * emb[v * ED + e];
    g_Q[i] = s;
}

// ---------------------------------------------------------------------------
// Persistent fused LSTM, gate-major warp tiles (m64 = 4 gates x 16 h, n16).
// 8 warps = 2 wm x 4 wn. Each thread holds ALL 4 gates for its 8 (h,b) cells ->
// cell update fully in registers; epilogue = shT transpose + store (2 syncs).
__global__ __launch_bounds__(256, 4) void lstm_persist() {
    extern __shared__ char smem[];
    const uint32_t sb = smem_u32(smem);
    const int tid = threadIdx.x;
    const int lane = tid & 31;
    const int warp = tid >> 5;
    const int wm = warp >> 2;           // m-half (0..1): rows wm*64..+63 (gate-major)
    const int wn = warp & 3;            // n-quarter (0..3): cols wn*16..+15
    const int n0 = wn * 16;
    const int bx = blockIdx.x;
    const int b0 = bx * NB;
    const int hblk = blockIdx.y;
    const int c0 = hblk >> 1;

    const __half* __restrict__ Wblk = &g_Wr[(size_t)hblk * 128 * HD];
    int* const myflag = &g_flag[((bx << 5) + hblk) << 5];

    // Q tile -> smem once (constant across t): sQ[g][v][hl], hl in [0,32)
    float* sQ = reinterpret_cast<float*>(smem + SQ_OFF);
    for (int i = tid; i < 4 * VD * 32; i += 256) {
        int g = i / (VD * 32), v = (i / 32) % VD, hl = i & 31;
        sQ[i] = g_Q[(g * VD + v) * HD + hblk * 32 + hl];
    }

    // cp.async staging (unchanged): A 4 units/thread, B 2 units/thread per stage.
    const int ur = tid >> 3;
    const int uc = tid & 7;
    const uint32_t sw_off = SW(ur, uc);

    // ldmatrix per-lane address components
    const int a_r = wm * 64 + (lane & 15);              // + g*16 per gate frag
    const int a_cadd = lane >> 4;
    const int b_radd = (lane & 7) + ((lane & 16) >> 1);
    const int b_cadd = (lane >> 3) & 1;

    // Epilogue cell-geometry (fixed across steps)
    const int r    = lane >> 2;         // 0..7
    const int qcol = lane & 3;          // 0..3

#pragma unroll 1
    for (int t = 0; t < TD; t++) {
        const __half* __restrict__ Bsrc =
            &g_hT2[(size_t)(t & 1) * BD * HD + (size_t)b0 * HD];
        __half* __restrict__ hTw = &g_hT2[(size_t)((t + 1) & 1) * BD * HD];

        // ---- prologue: gate on chunks c0, c0+1; prefetch stages 0,1 ----
        if (tid == 0) {
            wait_chunk(bx, c0, t);
            wait_chunk(bx, (c0 + 1) & (NCH - 1), t);
        }
        __syncthreads();
#pragma unroll
        for (int st = 0; st < 2; st++) {
            const int ch = (c0 + st) & (NCH - 1);
            const int koff = ch * BK;
            const uint32_t s0 = sb + st * STAGE_BYTES;
#pragma unroll
            for (int j = 0; j < 4; j++)
                cp16(s0 + sw_off + j * (32 * 128),
                     &Wblk[(size_t)(ur + j * 32) * HD + koff + uc * 8]);
#pragma unroll
            for (int j = 0; j < 2; j++)
                cp16(s0 + B_OFF + sw_off + j * (32 * 128),
                     &Bsrc[(size_t)(ur + j * 32) * HD + koff + uc * 8]);
            cp_commit();
        }

        // acc[g][nf][hh]: gate g, n8-slice nf, h-half hh. 16 regs.
        uint32_t acc[4][2][2];
#pragma unroll
        for (int g = 0; g < 4; g++)
#pragma unroll
            for (int j = 0; j < 2; j++) { acc[g][j][0] = 0u; acc[g][j][1] = 0u; }

        // ---- mainloop: 16 chunks rotated, 2-stage pipeline ----
#pragma unroll 1
        for (int i = 0; i < NCH; i++) {
            cp_wait<1>();
            __syncthreads();

            const uint32_t Ab = sb + (i & 1) * STAGE_BYTES;
            const uint32_t Bb = Ab + B_OFF;
#pragma unroll
            for (int ks = 0; ks < 4; ks++) {
                const int c16 = ks * 2;
                uint32_t a[4][4];
#pragma unroll
                for (int g = 0; g < 4; g++)
                    ldm_x4(a[g], Ab + SW(a_r + g * 16, c16 + a_cadd));
                uint32_t b[4];
                ldm_x4(b, Bb + SW(n0 + b_radd, c16 + b_cadd));
#pragma unroll
                for (int g = 0; g < 4; g++)
#pragma unroll
                    for (int nf = 0; nf < 2; nf++)
                        mma_f16acc(acc[g][nf], a[g], b[nf * 2], b[nf * 2 + 1]);
            }

            if (i + 2 < NCH && tid == 0)
                wait_chunk(bx, (c0 + i + 2) & (NCH - 1), t);
            __syncthreads();

            if (i + 2 < NCH) {
                const int ch = (c0 + i + 2) & (NCH - 1);
                const int koff = ch * BK;
                const uint32_t s0 = sb + (i & 1) * STAGE_BYTES;
#pragma unroll
                for (int j = 0; j < 4; j++)
                    cp16(s0 + sw_off + j * (32 * 128),
                         &Wblk[(size_t)(ur + j * 32) * HD + koff + uc * 8]);
#pragma unroll
                for (int j = 0; j < 2; j++)
                    cp16(s0 + B_OFF + sw_off + j * (32 * 128),
                         &Bsrc[(size_t)(ur + j * 32) * HD + koff + uc * 8]);
            }
            cp_commit();
        }
        cp_wait<0>();
        // All MMA stage reads synced at last chunk's post-MMA barrier. shT
        // overlays stage-0 smem (last read chunk 14, synced; no pending cp).

        // ---- register-fused cell update ----
        __half* shT = reinterpret_cast<__half*>(smem);   // [64][34]
        {
            const int* __restrict__ tokrow = &g_tokT[(size_t)t * BD + b0];
#pragma unroll
            for (int hh = 0; hh < 2; hh++) {
                const int h_loc  = wm * 16 + r + hh * 8;       // 0..31
                const int h_glob = hblk * 32 + h_loc;
                const float* q0 = &sQ[(0 * VD) * 32 + h_loc];  // stride 32 per v
                const float* q1 = &sQ[(1 * VD) * 32 + h_loc];
                const float* q2 = &sQ[(2 * VD) * 32 + h_loc];
                const float* q3 = &sQ[(3 * VD) * 32 + h_loc];
                float qg[3], qi[3], qf[3], qo[3];
#pragma unroll
                for (int v = 0; v < 3; v++) {
                    qg[v] = q0[v * 32]; qi[v] = q1[v * 32];
                    qf[v] = q2[v * 32]; qo[v] = q3[v * 32];
                }
#pragma unroll
                for (int nf = 0; nf < 2; nf++) {
                    const int bl = wn * 16 + nf * 8 + qcol * 2;   // local batch col
                    const size_t gidx = (size_t)h_glob * BD + b0 + bl;
                    float2 cold = *reinterpret_cast<const float2*>(&g_c[gidx]);
                    int2 tk = *reinterpret_cast<const int2*>(&tokrow[bl]);
                    float2 vg = __half22float2(*reinterpret_cast<const __half2*>(&acc[0][nf][hh]));
                    float2 vi = __half22float2(*reinterpret_cast<const __half2*>(&acc[1][nf][hh]));
                    float2 vf = __half22float2(*reinterpret_cast<const __half2*>(&acc[2][nf][hh]));
                    float2 vo = __half22float2(*reinterpret_cast<const __half2*>(&acc[3][nf][hh]));

                    float gg0 = ftanh(vg.x + qsel(qg, tk.x));
                    float ii0 = sigm (vi.x + qsel(qi, tk.x));
                    float ff0 = sigm (vf.x + qsel(qf, tk.x));
                    float oo0 = sigm (vo.x + qsel(qo, tk.x));
                    float c20 = gg0 * ii0 + cold.x * ff0;
                    float h20 = ftanh(c20) * oo0;

                    float gg1 = ftanh(vg.y + qsel(qg, tk.y));
                    float ii1 = sigm (vi.y + qsel(qi, tk.y));
                    float ff1 = sigm (vf.y + qsel(qf, tk.y));
                    float oo1 = sigm (vo.y + qsel(qo, tk.y));
                    float c21 = gg1 * ii1 + cold.y * ff1;
                    float h21 = ftanh(c21) * oo1;

                    *reinterpret_cast<float2*>(&g_c[gidx]) = make_float2(c20, c21);
                    shT[(size_t)bl * 34 + h_loc]       = __float2half(h20);
                    shT[(size_t)(bl + 1) * 34 + h_loc] = __float2half(h21);
                }
            }
        }
        __syncthreads();

        // ---- transposed fp16 write to the WRITE plane (coalesced uint4) ----
        {
            const int bl = tid >> 2;          // 0..63
            const int hs = (tid & 3) * 8;     // 8 h per thread
            uint32_t w[4];
#pragma unroll
            for (int i = 0; i < 4; i++) {
                uint32_t lo = (uint32_t)__half_as_ushort(shT[(size_t)bl * 34 + hs + 2 * i]);
                uint32_t hi = (uint32_t)__half_as_ushort(shT[(size_t)bl * 34 + hs + 2 * i + 1]);
                w[i] = lo | (hi << 16);
            }
            const size_t o = (size_t)(b0 + bl) * HD + hblk * 32 + hs;
            *reinterpret_cast<uint4*>(&hTw[o]) = make_uint4(w[0], w[1], w[2], w[3]);
        }

        // ---- publish h(t+1) ----
        __syncthreads();
        if (tid == 0) {
            __threadfence();
            st_rel(myflag, t + 1);
        }
    }
}

// ---------------------------------------------------------------------------
// Final projection p = W_ph @ h + b_p (C=10) + log_softmax; h in plane TD&1.
__global__ void proj_logsoftmax(const float* __restrict__ Wph,
                                const float* __restrict__ bp,
                                float* __restrict__ out) {
    int b = blockIdx.x * blockDim.x + threadIdx.x;
    if (b >= BD) return;
    float acc[CD];
#pragma unroll
    for (int c = 0; c < CD; c++) acc[c] = bp[c];
    const __half* hrow = &g_hT2[(size_t)(TD & 1) * BD * HD + (size_t)b * HD];
    for (int k = 0; k < HD; k++) {
        float hv = __half2float(hrow[k]);
#pragma unroll
        for (int c = 0; c < CD; c++) acc[c] = fmaf(Wph[c * HD + k], hv, acc[c]);
    }
    float m = acc[0];
#pragma unroll
    for (int c = 1; c < CD; c++) m = fmaxf(m, acc[c]);
    float s = 0.0f;
#pragma unroll
    for (int c = 0; c < CD; c++) s += expf(acc[c] - m);
    float lse = m + logf(s);
#pragma unroll
    for (int c = 0; c < CD; c++) out[b * CD + c] = acc[c] - lse;
}

// ---------------------------------------------------------------------------
extern "C" void kernel_launch(void* const* d_in, const int* in_sizes, int n_in,
                              void* d_out, int out_size) {
    const int*   x    = (const int*)  d_in[0];
    const float* emb  = (const float*)d_in[1];
    const float* W_gx = (const float*)d_in[2];
    const float* W_gh = (const float*)d_in[3];
    const float* b_g  = (const float*)d_in[4];
    const float* W_ix = (const float*)d_in[5];
    const float* W_ih = (const float*)d_in[6];
    const float* b_i  = (const float*)d_in[7];
    const float* W_fx = (const float*)d_in[8];
    const float* W_fh = (const float*)d_in[9];
    const float* b_f  = (const float*)d_in[10];
    const float* W_ox = (const float*)d_in[11];
    const float* W_oh = (const float*)d_in[12];
    const float* b_o  = (const float*)d_in[13];
    const float* W_ph = (const float*)d_in[14];
    const float* b_p  = (const float*)d_in[15];
    const float* h0   = (const float*)d_in[16];
    const float* c0   = (const float*)d_in[17];
    float* out = (float*)d_out;

    cudaFuncSetAttribute(lstm_persist, cudaFuncAttributeMaxDynamicSharedMemorySize,
                         SMEM_STEP);

    init_state<<<(HD * BD + 255) / 256, 256>>>(h0, c0, x);
    prep_weights<<<(32 * 128 * HD / 4 + 255) / 256, 256>>>(W_gh, W_ih, W_fh, W_oh);
    build_Q<<<(4 * VD * HD + 255) / 256, 256>>>(emb, W_gx, b_g, W_ix, b_i,
                                                W_fx, b_f, W_ox, b_o);

    dim3 grid(BD / NB, HD / 32);   // (16, 32) = 512 CTAs, all resident at 4/SM
    lstm_persist<<<grid, 256, SMEM_STEP>>>();

    proj_logsoftmax<<<(BD + 255) / 256, 256>>>(W_ph, b_p, out);
}

// round 17
// speedup vs baseline: 1.0638x; 1.0638x over previous
#include <cuda_runtime.h>
#include <cuda_fp16.h>
#include <math.h>
#include <stdint.h>

// Problem constants: H=1024, B=1024, S=128 (T=127), E=6, V=3, C=10
#define HD   1024
#define BD   1024
#define SD   128
#define TD   127
#define ED   6
#define VD   3
#define CD   10

#define NB   64       // batch cols per block
#define BK   64       // k per chunk
#define NCH  (HD/BK)  // 16 chunks

// Stage: A 128x64 f16 (16KB) + B 64x64 f16 (8KB) = 24KB; 2 stages = 48KB.
// sQ tile (4*3*32 f32 = 1536B) lives above the stages; 50.7KB <= 57KB (4 CTAs/SM).
#define STAGE_BYTES 24576
#define B_OFF       16384
#define SQ_OFF      (2 * STAGE_BYTES)
#define SMEM_STEP   (2 * STAGE_BYTES + 1536)

// ---------------------------------------------------------------------------
// Static device scratch (no allocations allowed).
__device__ __half g_Wr[32u * 128 * HD];   // rearranged fp16 weights [hblk][gate*32+hl][k]
__device__ __half g_hT2[2u * BD * HD];    // PING-PONG h transposed fp16 [plane][b][h]
__device__ float  g_c[HD * BD];           // cell state [h][b]
__device__ float  g_Q[4 * VD * HD];       // input contribution + bias [gate][v][h]
__device__ int    g_tokT[SD * BD];        // tokens transposed [t][b]
// Release flags: g_flag[(bx*32 + hblk)*32] = highest step published by (bx,hblk).
// Padded to 128B per flag (single writer each; readers acquire).
__device__ int    g_flag[16 * 32 * 32];

// ---------------------------------------------------------------------------
__device__ __forceinline__ uint32_t smem_u32(const void* p) {
    uint32_t a;
    asm("{ .reg .u64 t; cvta.to.shared.u64 t, %1; cvt.u32.u64 %0, t; }" : "=r"(a) : "l"(p));
    return a;
}

__device__ __forceinline__ void cp16(uint32_t dst, const void* src) {
    asm volatile("cp.async.cg.shared.global [%0], [%1], 16;" :: "r"(dst), "l"(src));
}
__device__ __forceinline__ void cp_commit() {
    asm volatile("cp.async.commit_group;" ::: "memory");
}
template <int N> __device__ __forceinline__ void cp_wait() {
    asm volatile("cp.async.wait_group %0;" :: "n"(N) : "memory");
}

__device__ __forceinline__ void ldm_x4(uint32_t r[4], uint32_t addr) {
    asm volatile("ldmatrix.sync.aligned.m8n8.x4.shared.b16 {%0,%1,%2,%3}, [%4];"
                 : "=r"(r[0]), "=r"(r[1]), "=r"(r[2]), "=r"(r[3]) : "r"(addr));
}

// f16-accumulate HMMA: D (2 regs, f16x2) = A (4 regs) * B (2 regs) + D.
__device__ __forceinline__ void mma_f16acc(uint32_t c[2], const uint32_t a[4],
                                           const uint32_t b0, const uint32_t b1) {
    asm volatile(
        "mma.sync.aligned.m16n8k16.row.col.f16.f16.f16.f16 "
        "{%0,%1}, {%2,%3,%4,%5}, {%6,%7}, {%0,%1};"
        : "+r"(c[0]), "+r"(c[1])
        : "r"(a[0]), "r"(a[1]), "r"(a[2]), "r"(a[3]), "r"(b0), "r"(b1));
}

__device__ __forceinline__ int ld_acq(const int* p) {
    int v;
    asm volatile("ld.acquire.gpu.s32 %0, [%1];" : "=r"(v) : "l"(p) : "memory");
    return v;
}
__device__ __forceinline__ void st_rel(int* p, int v) {
    asm volatile("st.release.gpu.s32 [%0], %1;" :: "l"(p), "r"(v) : "memory");
}
// Spin until one producer flag reaches step t.  (hblk index, not chunk.)
__device__ __forceinline__ void wait_flag(int bx, int hb, int t) {
    const int* f = &g_flag[((bx << 5) + hb) << 5];
    while (ld_acq(f) < t) __nanosleep(32);
}

__device__ __forceinline__ float sigm(float v) { return 1.0f / (1.0f + __expf(-v)); }
__device__ __forceinline__ float ftanh(float x) {
    float e = __expf(-2.0f * fabsf(x));
    float r = (1.0f - e) / (1.0f + e);
    return copysignf(r, x);
}
__device__ __forceinline__ float qsel(const float* q, int t) {
    return t == 0 ? q[0] : (t == 1 ? q[1] : q[2]);
}

// Swizzled byte offset inside a 128B-row tile: (r, c16) with c16 in [0,8)
__device__ __forceinline__ uint32_t SW(int r, int c16) {
    return (uint32_t)(r * 128) + ((uint32_t)(c16 << 4) ^ (uint32_t)((r & 7) << 4));
}

// ---------------------------------------------------------------------------
// One-time init kernels
__global__ void init_state(const float* __restrict__ h0, const float* __restrict__ c0,
                           const int* __restrict__ x) {
    int i = blockIdx.x * blockDim.x + threadIdx.x;
    if (i < HD * BD) {
        g_c[i] = c0[i];
        int h = i >> 10, b = i & (BD - 1);
        g_hT2[(size_t)b * HD + h] = __float2half(h0[i]);   // plane 0
    }
    if (i < SD * BD) {
        int t = i >> 10, b = i & (BD - 1);
        g_tokT[(size_t)t * BD + b] = x[(size_t)b * SD + t];
    }
    if (i < 16 * 32 * 32) g_flag[i] = 0;   // reset flags every run (graph replays)
}

// Rearranged fp16 weights: g_Wr[((y*128 + gate*32 + hl))*HD + k] = W_gate[(y*32+hl)*HD + k]
__global__ void prep_weights(const float* __restrict__ W0, const float* __restrict__ W1,
                             const float* __restrict__ W2, const float* __restrict__ W3) {
    size_t e = (size_t)(blockIdx.x * blockDim.x + threadIdx.x) * 4;
    if (e >= 32ull * 128 * HD) return;
    int k = (int)(e & (HD - 1));
    int r = (int)((e >> 10) & 127);
    int y = (int)(e >> 17);
    int gate = r >> 5;
    int h = y * 32 + (r & 31);
    const float* W = gate == 0 ? W0 : gate == 1 ? W1 : gate == 2 ? W2 : W3;
    float4 v = *reinterpret_cast<const float4*>(&W[(size_t)h * HD + k]);
    *reinterpret_cast<__half2*>(&g_Wr[e])     = __floats2half2_rn(v.x, v.y);
    *reinterpret_cast<__half2*>(&g_Wr[e + 2]) = __floats2half2_rn(v.z, v.w);
}

__global__ void build_Q(const float* __restrict__ emb,
                        const float* __restrict__ Wgx, const float* __restrict__ bg,
                        const float* __restrict__ Wix, const float* __restrict__ bi,
                        const float* __restrict__ Wfx, const float* __restrict__ bf,
                        const float* __restrict__ Wox, const float* __restrict__ bo) {
    int i = blockIdx.x * blockDim.x + threadIdx.x;
    if (i >= 4 * VD * HD) return;
    int gate = i / (VD * HD);
    int r = i % (VD * HD);
    int v = r >> 10;
    int h = r & (HD - 1);
    const float* Wx = (gate == 0) ? Wgx : (gate == 1) ? Wix : (gate == 2) ? Wfx : Wox;
    const float* bb = (gate == 0) ? bg  : (gate == 1) ? bi  : (gate == 2) ? bf  : bo;
    float s = bb[h];
#pragma unroll
    for (int e = 0; e < ED; e++) s += Wx[h * ED + e] * emb[v * ED + e];
    g_Q[i] = s;
}

// ---------------------------------------------------------------------------
// Persistent fused LSTM (R15 structure + micro-trims).
// Grid (16, 32) = 512 CTAs, 4/SM resident, one wave, deadlock-free.
// Rotated chunk order (c0 = hblk>>1); per-chunk producer flags; Q tile in smem;
// flag spins parallelized across threads.
__global__ __launch_bounds__(256, 4) void lstm_persist() {
    extern __shared__ char smem[];
    const uint32_t sb = smem_u32(smem);
    const int tid = threadIdx.x;
    const int lane = tid & 31;
    const int warp = tid >> 5;
    const int mg = warp >> 1;           // gate / m-group (0..3)
    const int wn = warp & 1;            // n-half (0..1)
    const int m0 = mg * 32;
    const int n0 = wn * 32;
    const int bx = blockIdx.x;
    const int b0 = bx * NB;
    const int hblk = blockIdx.y;
    const int c0 = hblk >> 1;           // own k-chunk

    const __half* __restrict__ Wblk = &g_Wr[(size_t)hblk * 128 * HD];
    int* const myflag = &g_flag[((bx << 5) + hblk) << 5];

    // Q tile -> smem once (constant across t): sQ[g*3 + v][hl], hl in [0,32)
    float* sQ = reinterpret_cast<float*>(smem + SQ_OFF);
    for (int i = tid; i < 4 * VD * 32; i += 256) {
        int gv = i >> 5, hl = i & 31;
        sQ[i] = g_Q[gv * HD + hblk * 32 + hl];
    }
    // (first prologue __syncthreads below orders this before any use)

    // cp.async staging: A 4 units/thread, B 2 units/thread per stage.
    const int ur = tid >> 3;            // 0..31
    const int uc = tid & 7;             // 16B column
    const uint32_t sw_off = SW(ur, uc);

    // ldmatrix per-lane address components
    const int a_r = m0 + (lane & 15);
    const int a_cadd = lane >> 4;
    const int b_radd = (lane & 7) + ((lane & 16) >> 1);
    const int b_cadd = (lane >> 3) & 1;

#pragma unroll 1
    for (int t = 0; t < TD; t++) {
        const __half* __restrict__ Bsrc =
            &g_hT2[(size_t)(t & 1) * BD * HD + (size_t)b0 * HD];
        __half* __restrict__ hTw = &g_hT2[(size_t)((t + 1) & 1) * BD * HD];

        // ---- prologue: gate on chunks c0, c0+1 (4 flags, one spinner each) ----
        if ((tid & 63) == 0 && tid < 256) {
            const int which = tid >> 6;                 // 0..3
            const int ch = (c0 + (which >> 1)) & (NCH - 1);
            wait_flag(bx, (ch << 1) + (which & 1), t);
        }
        __syncthreads();   // broadcast flag results; orders epilogue smem reuse + sQ
#pragma unroll
        for (int st = 0; st < 2; st++) {
            const int ch = (c0 + st) & (NCH - 1);
            const int koff = ch * BK;
            const uint32_t s0 = sb + st * STAGE_BYTES;
#pragma unroll
            for (int j = 0; j < 4; j++)
                cp16(s0 + sw_off + j * (32 * 128),
                     &Wblk[(size_t)(ur + j * 32) * HD + koff + uc * 8]);
#pragma unroll
            for (int j = 0; j < 2; j++)
                cp16(s0 + B_OFF + sw_off + j * (32 * 128),
                     &Bsrc[(size_t)(ur + j * 32) * HD + koff + uc * 8]);
            cp_commit();
        }

        uint32_t acc[2][4][2];
#pragma unroll
        for (int i = 0; i < 2; i++)
#pragma unroll
            for (int j = 0; j < 4; j++) { acc[i][j][0] = 0u; acc[i][j][1] = 0u; }

        // ---- mainloop: 16 chunks rotated, 2-stage pipeline ----
#pragma unroll 1
        for (int i = 0; i < NCH; i++) {
            cp_wait<1>();
            __syncthreads();

            const uint32_t Ab = sb + (i & 1) * STAGE_BYTES;
            const uint32_t Bb = Ab + B_OFF;
#pragma unroll
            for (int ks = 0; ks < 4; ks++) {
                const int c16 = ks * 2;
                uint32_t a[2][4];
#pragma unroll
                for (int mf = 0; mf < 2; mf++)
                    ldm_x4(a[mf], Ab + SW(a_r + mf * 16, c16 + a_cadd));
                uint32_t b[2][4];
#pragma unroll
                for (int p = 0; p < 2; p++)
                    ldm_x4(b[p], Bb + SW(n0 + p * 16 + b_radd, c16 + b_cadd));
#pragma unroll
                for (int mf = 0; mf < 2; mf++)
#pragma unroll
                    for (int nf = 0; nf < 4; nf++)
                        mma_f16acc(acc[mf][nf], a[mf], b[nf >> 1][(nf & 1) * 2],
                                   b[nf >> 1][(nf & 1) * 2 + 1]);
            }

            // flag check for chunk i+2, two parallel spinners (t0: f0, t32: f1)
            if (i + 2 < NCH && (tid == 0 || tid == 32)) {
                const int ch = (c0 + i + 2) & (NCH - 1);
                wait_flag(bx, (ch << 1) + (tid >> 5), t);
            }
            __syncthreads();   // stage reading done + flag broadcast

            if (i + 2 < NCH) {
                const int ch = (c0 + i + 2) & (NCH - 1);
                const int koff = ch * BK;
                const uint32_t s0 = sb + (i & 1) * STAGE_BYTES;
#pragma unroll
                for (int j = 0; j < 4; j++)
                    cp16(s0 + sw_off + j * (32 * 128),
                         &Wblk[(size_t)(ur + j * 32) * HD + koff + uc * 8]);
#pragma unroll
                for (int j = 0; j < 2; j++)
                    cp16(s0 + B_OFF + sw_off + j * (32 * 128),
                         &Bsrc[(size_t)(ur + j * 32) * HD + koff + uc * 8]);
            }
            cp_commit();   // one group per iteration keeps wait<1> exact
        }
        __syncthreads();   // protect stage smem before reuse as epilogue scratch

        // ---- Epilogue pass 1: acc (f16x2) -> smem gate planes [4][32][68] f32 ----
        float* spre = reinterpret_cast<float*>(smem);
#pragma unroll
        for (int mf = 0; mf < 2; mf++) {
            const int row = mf * 16 + (lane >> 2);
#pragma unroll
            for (int nf = 0; nf < 4; nf++) {
                const int col = n0 + nf * 8 + (lane & 3) * 2;
                float* pl = &spre[(size_t)(mg * 32 + row) * 68 + col];
                float2 f01 = __half22float2(*reinterpret_cast<const __half2*>(&acc[mf][nf][0]));
                float2 f23 = __half22float2(*reinterpret_cast<const __half2*>(&acc[mf][nf][1]));
                *reinterpret_cast<float2*>(pl)          = f01;
                *reinterpret_cast<float2*>(pl + 8 * 68) = f23;
            }
        }
        __syncthreads();

        // ---- Epilogue pass 2: cell update (Q from smem) ----
        __half* shT = reinterpret_cast<__half*>(smem + 4 * 32 * 68 * 4); // [64][34]
        {
            const int hl = tid >> 3;
            const int bs = (tid & 7) * 8;
            const int h = hblk * 32 + hl;
            float q[4][3];
#pragma unroll
            for (int g = 0; g < 4; g++)
#pragma unroll
                for (int v = 0; v < 3; v++) q[g][v] = sQ[(g * VD + v) * 32 + hl];

            const float* p0 = &spre[(size_t)(0 * 32 + hl) * 68];
            const float* p1 = &spre[(size_t)(1 * 32 + hl) * 68];
            const float* p2 = &spre[(size_t)(2 * 32 + hl) * 68];
            const float* p3 = &spre[(size_t)(3 * 32 + hl) * 68];
            const int* __restrict__ tokrow = &g_tokT[(size_t)t * BD + b0];

#pragma unroll
            for (int j = 0; j < 8; j += 4) {
                const int bl = bs + j;
                const size_t gidx = (size_t)h * BD + b0 + bl;
                float4 cold = *reinterpret_cast<const float4*>(&g_c[gidx]);
                float4 vg = *reinterpret_cast<const float4*>(&p0[bl]);
                float4 vi = *reinterpret_cast<const float4*>(&p1[bl]);
                float4 vf = *reinterpret_cast<const float4*>(&p2[bl]);
                float4 vo = *reinterpret_cast<const float4*>(&p3[bl]);
                int4 tkv = *reinterpret_cast<const int4*>(&tokrow[bl]);
                int tk[4] = {tkv.x, tkv.y, tkv.z, tkv.w};

                float vgx[4] = {vg.x, vg.y, vg.z, vg.w};
                float vix[4] = {vi.x, vi.y, vi.z, vi.w};
                float vfx[4] = {vf.x, vf.y, vf.z, vf.w};
                float vox[4] = {vo.x, vo.y, vo.z, vo.w};
                float cox[4] = {cold.x, cold.y, cold.z, cold.w};
                float c2[4], h2[4];
#pragma unroll
                for (int i = 0; i < 4; i++) {
                    float gg = ftanh(vgx[i] + qsel(q[0], tk[i]));
                    float ii = sigm (vix[i] + qsel(q[1], tk[i]));
                    float ff = sigm (vfx[i] + qsel(q[2], tk[i]));
                    float oo = sigm (vox[i] + qsel(q[3], tk[i]));
                    c2[i] = gg * ii + cox[i] * ff;
                    h2[i] = ftanh(c2[i]) * oo;
                }
                *reinterpret_cast<float4*>(&g_c[gidx]) = make_float4(c2[0], c2[1], c2[2], c2[3]);
#pragma unroll
                for (int i = 0; i < 4; i++)
                    shT[(size_t)(bl + i) * 34 + hl] = __float2half(h2[i]);
            }
        }
        __syncthreads();

        // ---- Epilogue pass 3: transposed fp16 write to the WRITE plane ----
        {
            const int bl = tid >> 2;
            const int hs = (tid & 3) * 8;
            uint32_t w[4];
#pragma unroll
            for (int i = 0; i < 4; i++) {
                uint32_t lo = (uint32_t)__half_as_ushort(shT[(size_t)bl * 34 + hs + 2 * i]);
                uint32_t hi = (uint32_t)__half_as_ushort(shT[(size_t)bl * 34 + hs + 2 * i + 1]);
                w[i] = lo | (hi << 16);
            }
            const size_t o = (size_t)(b0 + bl) * HD + hblk * 32 + hs;
            *reinterpret_cast<uint4*>(&hTw[o]) = make_uint4(w[0], w[1], w[2], w[3]);
        }

        // ---- publish h(t+1) (skipped on the final step: no consumer) ----
        if (t + 1 < TD) {
            __syncthreads();
            if (tid == 0) {
                __threadfence();             // order all threads' hT stores (post-bar)
                st_rel(myflag, t + 1);
            }
        }
    }
}

// ---------------------------------------------------------------------------
// Final projection p = W_ph @ h + b_p (C=10) + log_softmax; h in plane TD&1.
__global__ void proj_logsoftmax(const float* __restrict__ Wph,
                                const float* __restrict__ bp,
                                float* __restrict__ out) {
    int b = blockIdx.x * blockDim.x + threadIdx.x;
    if (b >= BD) return;
    float acc[CD];
#pragma unroll
    for (int c = 0; c < CD; c++) acc[c] = bp[c];
    const __half* hrow = &g_hT2[(size_t)(TD & 1) * BD * HD + (size_t)b * HD];
    for (int k = 0; k < HD; k++) {
        float hv = __half2float(hrow[k]);
#pragma unroll
        for (int c = 0; c < CD; c++) acc[c] = fmaf(Wph[c * HD + k], hv, acc[c]);
    }
    float m = acc[0];
#pragma unroll
    for (int c = 1; c < CD; c++) m = fmaxf(m, acc[c]);
    float s = 0.0f;
#pragma unroll
    for (int c = 0; c < CD; c++) s += expf(acc[c] - m);
    float lse = m + logf(s);
#pragma unroll
    for (int c = 0; c < CD; c++) out[b * CD + c] = acc[c] - lse;
}

// ---------------------------------------------------------------------------
extern "C" void kernel_launch(void* const* d_in, const int* in_sizes, int n_in,
                              void* d_out, int out_size) {
    const int*   x    = (const int*)  d_in[0];
    const float* emb  = (const float*)d_in[1];
    const float* W_gx = (const float*)d_in[2];
    const float* W_gh = (const float*)d_in[3];
    const float* b_g  = (const float*)d_in[4];
    const float* W_ix = (const float*)d_in[5];
    const float* W_ih = (const float*)d_in[6];
    const float* b_i  = (const float*)d_in[7];
    const float* W_fx = (const float*)d_in[8];
    const float* W_fh = (const float*)d_in[9];
    const float* b_f  = (const float*)d_in[10];
    const float* W_ox = (const float*)d_in[11];
    const float* W_oh = (const float*)d_in[12];
    const float* b_o  = (const float*)d_in[13];
    const float* W_ph = (const float*)d_in[14];
    const float* b_p  = (const float*)d_in[15];
    const float* h0   = (const float*)d_in[16];
    const float* c0   = (const float*)d_in[17];
    float* out = (float*)d_out;

    cudaFuncSetAttribute(lstm_persist, cudaFuncAttributeMaxDynamicSharedMemorySize,
                         SMEM_STEP);

    init_state<<<(HD * BD + 255) / 256, 256>>>(h0, c0, x);
    prep_weights<<<(32 * 128 * HD / 4 + 255) / 256, 256>>>(W_gh, W_ih, W_fh, W_oh);
    build_Q<<<(4 * VD * HD + 255) / 256, 256>>>(emb, W_gx, b_g, W_ix, b_i,
                                                W_fx, b_f, W_ox, b_o);

    dim3 grid(BD / NB, HD / 32);   // (16, 32) = 512 CTAs, all resident at 4/SM
    lstm_persist<<<grid, 256, SMEM_STEP>>>();

    proj_logsoftmax<<<(BD + 255) / 256, 256>>>(W_ph, b_p, out);
}